// round 13
// baseline (speedup 1.0000x reference)
#include <cuda_runtime.h>

#define BB 1024
#define SS 192
#define DD 512
#define NLAYERS 3
#define LN_EPS 1e-5f

// Allocation-free scratch (device globals, permitted by harness rules).
__device__ int   g_start[BB];
__device__ int   g_end[BB];
__device__ float g_add[SS * DD];   // combined add table: [pos][d]

// ---------------------------------------------------------------------------
// Kernel 1 (fused prologue):
//   blocks [0, ADD_BLOCKS)          : build g_add table
//   blocks [ADD_BLOCKS, +BND_BLOCKS): per-batch start/end from mask
// ---------------------------------------------------------------------------
#define ADD_BLOCKS ((SS * DD + 255) / 256)     // 384
#define BND_BLOCKS ((BB + 7) / 8)              // 128 (8 warps/block, 1 batch/warp)

__global__ void prologue_kernel(const int*   __restrict__ mask,
                                const float* __restrict__ item,
                                const float* __restrict__ layer,
                                const float* __restrict__ temporal) {
    if (blockIdx.x < ADD_BLOCKS) {
        int idx = blockIdx.x * blockDim.x + threadIdx.x;
        if (idx >= SS * DD) return;
        int pos = idx / DD;
        int d   = idx % DD;
        int it  = pos / NLAYERS;
        int ly  = pos % NLAYERS;
        g_add[idx] = item[it * DD + d] + layer[ly * DD + d] + temporal[it * DD + d];
        return;
    }

    // bounds part: one warp per batch row
    int blk  = blockIdx.x - ADD_BLOCKS;
    int b    = blk * (blockDim.x >> 5) + (threadIdx.x >> 5);
    int lane = threadIdx.x & 31;
    if (b >= BB) return;
    const int* m = mask + b * SS;

    int start = SS;
    int end   = 0;
#pragma unroll
    for (int c = 0; c < SS / 32; ++c) {
        int v = m[c * 32 + lane];
        unsigned bal = __ballot_sync(0xffffffffu, v != 0);
        if (bal) {
            int first = c * 32 + __ffs(bal) - 1;
            int last  = c * 32 + 31 - __clz(bal);
            if (start == SS) start = first;
            end = last + 1;
        }
    }
    if (lane == 0) {
        g_start[b] = start;
        g_end[b]   = end;
    }
}

// ---------------------------------------------------------------------------
// Kernel 2: fused add + LayerNorm + mask. One warp per (b,s) row.
// Mask-free: contiguous left-padding means mask!=0 <=> start <= s < end,
// derived from the L1-hot bounds tables.
// __launch_bounds__(256, 8): cap regs at 32 -> 8 blocks/SM, 100% static occ.
// ---------------------------------------------------------------------------
__global__ __launch_bounds__(256, 8) void fused_kernel(
    const float* __restrict__ tok,
    const float* __restrict__ w,
    const float* __restrict__ bias,
    float*       __restrict__ out)
{
    int gwarp = (blockIdx.x * blockDim.x + threadIdx.x) >> 5;
    int lane  = threadIdx.x & 31;
    if (gwarp >= BB * SS) return;

    int b = gwarp / SS;
    int s = gwarp % SS;
    size_t base = (size_t)gwarp * DD;
    float4* o = (float4*)(out + base);

    int st = g_start[b];
    int en = g_end[b];
    bool active = (s >= st) && (s < en);   // == (mask != 0) == in_range

    if (!active) {
        // output = normed * 0 -> just write zeros, skip the token read.
        float4 z = make_float4(0.f, 0.f, 0.f, 0.f);
#pragma unroll
        for (int k = 0; k < 4; ++k) __stcs(&o[lane + k * 32], z);
        return;
    }

    int pos = s - st;

    const float4* t = (const float4*)(tok + base);
    const float4* a = (const float4*)(g_add + pos * DD);

    float4 e[4];
#pragma unroll
    for (int k = 0; k < 4; ++k) e[k] = __ldcs(&t[lane + k * 32]);

#pragma unroll
    for (int k = 0; k < 4; ++k) {
        float4 av = __ldg(&a[lane + k * 32]);
        e[k].x += av.x; e[k].y += av.y; e[k].z += av.z; e[k].w += av.w;
    }

    float sum = 0.f, sq = 0.f;
#pragma unroll
    for (int k = 0; k < 4; ++k) {
        sum += e[k].x + e[k].y + e[k].z + e[k].w;
        sq  += e[k].x * e[k].x + e[k].y * e[k].y
             + e[k].z * e[k].z + e[k].w * e[k].w;
    }
#pragma unroll
    for (int off = 16; off >= 1; off >>= 1) {
        sum += __shfl_xor_sync(0xffffffffu, sum, off);
        sq  += __shfl_xor_sync(0xffffffffu, sq,  off);
    }

    const float inv_d = 1.0f / (float)DD;
    float mu   = sum * inv_d;
    float var  = sq * inv_d - mu * mu;
    float rstd = rsqrtf(var + LN_EPS);

    const float4* wv = (const float4*)w;
    const float4* bv = (const float4*)bias;
#pragma unroll
    for (int k = 0; k < 4; ++k) {
        float4 W  = __ldg(&wv[lane + k * 32]);
        float4 Bv = __ldg(&bv[lane + k * 32]);
        float4 r;
        r.x = (e[k].x - mu) * rstd * W.x + Bv.x;
        r.y = (e[k].y - mu) * rstd * W.y + Bv.y;
        r.z = (e[k].z - mu) * rstd * W.z + Bv.z;
        r.w = (e[k].w - mu) * rstd * W.w + Bv.w;
        __stcs(&o[lane + k * 32], r);
    }
}

// ---------------------------------------------------------------------------
// Launch
// ---------------------------------------------------------------------------
extern "C" void kernel_launch(void* const* d_in, const int* in_sizes, int n_in,
                              void* d_out, int out_size) {
    const float* tok      = (const float*)d_in[0];
    const int*   mask     = (const int*)  d_in[1];
    const float* item     = (const float*)d_in[2];
    const float* layer    = (const float*)d_in[3];
    const float* temporal = (const float*)d_in[4];
    const float* w        = (const float*)d_in[5];
    const float* bias     = (const float*)d_in[6];
    float*       out      = (float*)d_out;

    prologue_kernel<<<ADD_BLOCKS + BND_BLOCKS, 256>>>(mask, item, layer, temporal);

    int rows = BB * SS;                // one warp per row
    int warps_per_block = 256 / 32;    // 8
    int blocks = (rows + warps_per_block - 1) / warps_per_block;
    fused_kernel<<<blocks, 256>>>(tok, w, bias, out);
}

// round 14
// speedup vs baseline: 1.0389x; 1.0389x over previous
#include <cuda_runtime.h>

#define BB 1024
#define SS 192
#define DD 512
#define NLAYERS 3
#define LN_EPS 1e-5f

// Allocation-free scratch (device globals, permitted by harness rules).
__device__ int   g_start[BB];
__device__ int   g_end[BB];
__device__ float g_add[SS * DD];   // combined add table: [pos][d]

// ---------------------------------------------------------------------------
// Kernel 1 (fused prologue):
//   blocks [0, ADD_BLOCKS)          : build g_add table
//   blocks [ADD_BLOCKS, +BND_BLOCKS): per-batch start/end from mask
// ---------------------------------------------------------------------------
#define ADD_BLOCKS ((SS * DD + 255) / 256)     // 384
#define BND_BLOCKS ((BB + 7) / 8)              // 128 (8 warps/block, 1 batch/warp)

__global__ void prologue_kernel(const int*   __restrict__ mask,
                                const float* __restrict__ item,
                                const float* __restrict__ layer,
                                const float* __restrict__ temporal) {
    if (blockIdx.x < ADD_BLOCKS) {
        int idx = blockIdx.x * blockDim.x + threadIdx.x;
        if (idx >= SS * DD) return;
        int pos = idx / DD;
        int d   = idx % DD;
        int it  = pos / NLAYERS;
        int ly  = pos % NLAYERS;
        g_add[idx] = item[it * DD + d] + layer[ly * DD + d] + temporal[it * DD + d];
        return;
    }

    // bounds part: one warp per batch row
    int blk  = blockIdx.x - ADD_BLOCKS;
    int b    = blk * (blockDim.x >> 5) + (threadIdx.x >> 5);
    int lane = threadIdx.x & 31;
    if (b >= BB) return;
    const int* m = mask + b * SS;

    int start = SS;
    int end   = 0;
#pragma unroll
    for (int c = 0; c < SS / 32; ++c) {
        int v = m[c * 32 + lane];
        unsigned bal = __ballot_sync(0xffffffffu, v != 0);
        if (bal) {
            int first = c * 32 + __ffs(bal) - 1;
            int last  = c * 32 + 31 - __clz(bal);
            if (start == SS) start = first;
            end = last + 1;
        }
    }
    if (lane == 0) {
        g_start[b] = start;
        g_end[b]   = end;
    }
}

// ---------------------------------------------------------------------------
// Kernel 2: fused add + LayerNorm + mask. One warp per (b,s) row.
// Mask-free predicate from L1-hot bounds tables (contiguous left-padding).
// w/bias staged in shared memory once per block: cuts per-warp LDG count
// from 16 to 8, relieving L1tex wavefront pressure on the DRAM stream path.
// __launch_bounds__(256, 6): regs capped at 42 (best measured envelope).
// ---------------------------------------------------------------------------
__global__ __launch_bounds__(256, 6) void fused_kernel(
    const float* __restrict__ tok,
    const float* __restrict__ w,
    const float* __restrict__ bias,
    float*       __restrict__ out)
{
    __shared__ float s_w[DD];
    __shared__ float s_b[DD];

    int tid = threadIdx.x;
    // 256 threads load 512+512 floats: 2 per thread per array.
    s_w[tid]       = __ldg(w + tid);
    s_w[tid + 256] = __ldg(w + tid + 256);
    s_b[tid]       = __ldg(bias + tid);
    s_b[tid + 256] = __ldg(bias + tid + 256);
    __syncthreads();

    int gwarp = (blockIdx.x * blockDim.x + tid) >> 5;
    int lane  = tid & 31;
    if (gwarp >= BB * SS) return;

    int b = gwarp / SS;
    int s = gwarp % SS;
    size_t base = (size_t)gwarp * DD;
    float4* o = (float4*)(out + base);

    int st = g_start[b];
    int en = g_end[b];
    bool active = (s >= st) && (s < en);   // == (mask != 0) == in_range

    if (!active) {
        // output = normed * 0 -> just write zeros, skip the token read.
        float4 z = make_float4(0.f, 0.f, 0.f, 0.f);
#pragma unroll
        for (int k = 0; k < 4; ++k) __stcs(&o[lane + k * 32], z);
        return;
    }

    int pos = s - st;

    const float4* t = (const float4*)(tok + base);
    const float4* a = (const float4*)(g_add + pos * DD);

    float4 e[4];
#pragma unroll
    for (int k = 0; k < 4; ++k) e[k] = __ldcs(&t[lane + k * 32]);

#pragma unroll
    for (int k = 0; k < 4; ++k) {
        float4 av = __ldg(&a[lane + k * 32]);
        e[k].x += av.x; e[k].y += av.y; e[k].z += av.z; e[k].w += av.w;
    }

    float sum = 0.f, sq = 0.f;
#pragma unroll
    for (int k = 0; k < 4; ++k) {
        sum += e[k].x + e[k].y + e[k].z + e[k].w;
        sq  += e[k].x * e[k].x + e[k].y * e[k].y
             + e[k].z * e[k].z + e[k].w * e[k].w;
    }
#pragma unroll
    for (int off = 16; off >= 1; off >>= 1) {
        sum += __shfl_xor_sync(0xffffffffu, sum, off);
        sq  += __shfl_xor_sync(0xffffffffu, sq,  off);
    }

    const float inv_d = 1.0f / (float)DD;
    float mu   = sum * inv_d;
    float var  = sq * inv_d - mu * mu;
    float rstd = rsqrtf(var + LN_EPS);

    const float4* swv = (const float4*)s_w;
    const float4* sbv = (const float4*)s_b;
#pragma unroll
    for (int k = 0; k < 4; ++k) {
        float4 W  = swv[lane + k * 32];
        float4 Bv = sbv[lane + k * 32];
        float4 r;
        r.x = (e[k].x - mu) * rstd * W.x + Bv.x;
        r.y = (e[k].y - mu) * rstd * W.y + Bv.y;
        r.z = (e[k].z - mu) * rstd * W.z + Bv.z;
        r.w = (e[k].w - mu) * rstd * W.w + Bv.w;
        __stcs(&o[lane + k * 32], r);
    }
}

// ---------------------------------------------------------------------------
// Launch
// ---------------------------------------------------------------------------
extern "C" void kernel_launch(void* const* d_in, const int* in_sizes, int n_in,
                              void* d_out, int out_size) {
    const float* tok      = (const float*)d_in[0];
    const int*   mask     = (const int*)  d_in[1];
    const float* item     = (const float*)d_in[2];
    const float* layer    = (const float*)d_in[3];
    const float* temporal = (const float*)d_in[4];
    const float* w        = (const float*)d_in[5];
    const float* bias     = (const float*)d_in[6];
    float*       out      = (float*)d_out;

    prologue_kernel<<<ADD_BLOCKS + BND_BLOCKS, 256>>>(mask, item, layer, temporal);

    int rows = BB * SS;                // one warp per row
    int warps_per_block = 256 / 32;    // 8
    int blocks = (rows + warps_per_block - 1) / warps_per_block;
    fused_kernel<<<blocks, 256>>>(tok, w, bias, out);
}